// round 17
// baseline (speedup 1.0000x reference)
#include <cuda_runtime.h>
#include <cuda_fp16.h>
#include <cstdint>

// R16: break the L2 W-stream bandwidth cap (100 MB/step at ~6000 B/cyc was the
// binding constraint). 128 CTAs x 512 threads x 64 batch rows, 1 CTA/SM,
// 16 warps each owning ONE feature group -> W read once per CTA-step = 50 MB/step.
// Register fit via f16-accumulate MMA for r,z gates (n-gate stays f32).

#define T_STEPS  180
#define NCTA     128
#define NTHR     512
#define MROWS    64                  // batch rows per CTA
#define HP       264                 // padded fp16 elems per h row
#define HROW     (HP*2)              // 528 bytes per h row
#define HBUF     (MROWS*HROW)        // 33792 B : one fp16 plane, 64 rows

#define OFF_HA   0
#define OFF_HB   HBUF                // 33792
#define OFF_BSR  (2*HBUF)            // 67584
#define OFF_BSZ  (OFF_BSR+1024)
#define OFF_BIN  (OFF_BSZ+1024)
#define OFF_BHN  (OFF_BIN+1024)
#define OFF_OW   (OFF_BHN+1024)      // 71680
#define OFF_OB   (OFF_OW+2048)       // 73728
#define OFF_OUT  (OFF_OB+16)         // 73744 ; 64*20*2 f32 = 10240
#define SMEM_SZ  (OFF_OUT+10240)     // 83984 B

// W in HMMA A-fragment order: [g(16)][ks(16)][mt(3)][lane(32)] uint4 (fp16)
__device__ __align__(16) uint4 g_wah[16*16*3*32];

__device__ __forceinline__ uint32_t smem_u32(const void* p) {
    uint32_t a;
    asm("{ .reg .u64 t; cvta.to.shared.u64 t, %1; cvt.u32.u64 %0, t; }" : "=r"(a) : "l"(p));
    return a;
}
__device__ __forceinline__ void ldsm4(uint32_t* r, uint32_t addr) {
    asm volatile("ldmatrix.sync.aligned.m8n8.x4.shared.b16 {%0,%1,%2,%3}, [%4];"
        : "=r"(r[0]), "=r"(r[1]), "=r"(r[2]), "=r"(r[3]) : "r"(addr));
}
// f32-accumulate (n gate)
__device__ __forceinline__ void mma_f16(float& d0, float& d1, float& d2, float& d3,
                                        uint32_t a0, uint32_t a1, uint32_t a2, uint32_t a3,
                                        uint32_t b0, uint32_t b1) {
    asm volatile("mma.sync.aligned.m16n8k16.row.col.f32.f16.f16.f32 "
        "{%0,%1,%2,%3},{%4,%5,%6,%7},{%8,%9},{%0,%1,%2,%3};"
        : "+f"(d0), "+f"(d1), "+f"(d2), "+f"(d3)
        : "r"(a0), "r"(a1), "r"(a2), "r"(a3), "r"(b0), "r"(b1));
}
// f16-accumulate (r,z gates) : D = {row gr, row gr+8} as packed (col,col+1) f16x2
__device__ __forceinline__ void mma_f16acc(uint32_t& d0, uint32_t& d1,
                                           uint32_t a0, uint32_t a1, uint32_t a2, uint32_t a3,
                                           uint32_t b0, uint32_t b1) {
    asm volatile("mma.sync.aligned.m16n8k16.row.col.f16.f16.f16.f16 "
        "{%0,%1},{%2,%3,%4,%5},{%6,%7},{%0,%1};"
        : "+r"(d0), "+r"(d1)
        : "r"(a0), "r"(a1), "r"(a2), "r"(a3), "r"(b0), "r"(b1));
}
__device__ __forceinline__ __half2 tanh2(__half2 x){
    uint32_t xi = *reinterpret_cast<uint32_t*>(&x), yi;
    asm("tanh.approx.f16x2 %0, %1;" : "=r"(yi) : "r"(xi));
    return *reinterpret_cast<__half2*>(&yi);
}
__device__ __forceinline__ float tanhf_acc(float x){  // accurate (h0 only)
    return 2.0f/(1.0f + __expf(-2.0f*x)) - 1.0f;
}

// ---------- prep: w_hh [768][256] fp32 -> fp16, A-fragment order ----------
__global__ void prep_w(const float* __restrict__ w) {
    int idx = blockIdx.x * 256 + threadIdx.x;         // 96*256 = 24576
    int l  = idx & 31;
    int r1 = idx >> 5;
    int mt = r1 % 3;  r1 /= 3;
    int ks = r1 & 15; int g = r1 >> 4;
    int gr = l >> 2, tig = l & 3;
    uint32_t hreg[4];
    #pragma unroll
    for (int rg = 0; rg < 4; rg++) {
        uint32_t hv = 0;
        #pragma unroll
        for (int hh = 0; hh < 2; hh++) {
            int i   = rg*2 + hh;
            int row = gr + 8*((i >> 1) & 1);
            int col = 2*tig + (i & 1) + 8*(i >> 2);
            float x = w[(mt*256 + g*16 + row)*256 + ks*16 + col];
            hv |= (uint32_t)__half_as_ushort(__float2half_rn(x)) << (16*hh);
        }
        hreg[rg] = hv;
    }
    g_wah[idx] = make_uint4(hreg[0], hreg[1], hreg[2], hreg[3]);
}

__global__ __launch_bounds__(NTHR, 1)
void gru_hmma_kernel(const float* __restrict__ z,
                     const float* __restrict__ fc_w,
                     const float* __restrict__ fc_b,
                     const float* __restrict__ b_ih,
                     const float* __restrict__ b_hh,
                     const float* __restrict__ out_w,
                     const float* __restrict__ out_b,
                     float* __restrict__ out)
{
    extern __shared__ char sm[];
    const uint32_t sbase = smem_u32(sm);
    const int tid = threadIdx.x;
    const int w   = tid >> 5;          // 16 warps, warp w owns feature group g=w
    const int l   = tid & 31;
    const int gr  = l >> 2, tig = l & 3;
    const int mbase = blockIdx.x * MROWS;

    float* bsr = (float*)(sm + OFF_BSR);
    float* bsz = (float*)(sm + OFF_BSZ);
    float* bin = (float*)(sm + OFF_BIN);
    float* bhn = (float*)(sm + OFF_BHN);
    float* ow  = (float*)(sm + OFF_OW);
    float* ob  = (float*)(sm + OFF_OB);
    float* obuf= (float*)(sm + OFF_OUT);

    // biases / output weights
    if (tid < 256) {
        int i = tid;
        bsr[i] = b_ih[i]       + b_hh[i];
        bsz[i] = b_ih[256 + i] + b_hh[256 + i];
        bin[i] = b_ih[512 + i];
        bhn[i] = b_hh[512 + i];
        ow[i]       = out_w[i];
        ow[256 + i] = out_w[256 + i];
        if (i < 2) ob[i] = out_b[i];
    }

    // ---- stage z [64][128] f32 into HB region, compute h0 into HA (fp16) ----
    {
        float* zs = (float*)(sm + OFF_HB);
        const float4* zp = (const float4*)(z + (size_t)mbase * 128);
        for (int i = tid; i < 2048; i += NTHR) ((float4*)zs)[i] = zp[i];
        __syncthreads();

        const int j    = tid & 255;        // feature
        const int half = tid >> 8;         // row half: 0 -> rows 0-31, 1 -> 32-63
        float acc[32];
        #pragma unroll
        for (int m = 0; m < 32; m++) acc[m] = 0.f;
        const float* wr = fc_w + (size_t)j * 128;
        const float* zh = zs + half*32*128;
        for (int k8 = 0; k8 < 16; k8++) {
            float4 wa = *(const float4*)(wr + k8*8);
            float4 wb = *(const float4*)(wr + k8*8 + 4);
            #pragma unroll
            for (int m = 0; m < 32; m++) {
                const float* zr = zh + m*128 + k8*8;
                float4 za = *(const float4*)zr;
                float4 zc = *(const float4*)(zr + 4);
                acc[m] += za.x*wa.x + za.y*wa.y + za.z*wa.z + za.w*wa.w
                        + zc.x*wb.x + zc.y*wb.y + zc.z*wb.z + zc.w*wb.w;
            }
        }
        float fb = fc_b[j];
        unsigned short* HH = (unsigned short*)(sm + OFF_HA);
        for (int m = 0; m < 32; m++) {
            float h = tanhf_acc(acc[m] + fb);
            HH[(half*32 + m)*HP + j] = __half_as_ushort(__float2half_rn(h));
        }
        __syncthreads();
    }

    // per-lane ldmatrix row offset (mapping validated in R6)
    const uint32_t rowoff = (uint32_t)(((l & 7) + 8*((l >> 4) & 1)) * HROW + ((l >> 3) & 1) * 16);

    const uint4* pH = g_wah + (size_t)(w*16)*96 + l;     // this warp's tile
    const __half2 h05 = __floats2half2_rn(0.5f, 0.5f);

    uint32_t cur = OFF_HA, nxt = OFF_HB;

    // prime 2-deep A-fragment ring
    uint4 af[2][3];
    af[0][0] = pH[0];    af[0][1] = pH[32];    af[0][2] = pH[64];
    af[1][0] = pH[96];   af[1][1] = pH[96+32]; af[1][2] = pH[96+64];

    for (int t = 0; t < T_STEPS; t++) {
        const uint32_t curb = sbase + cur;

        // acc: r,z in f16x2 (d0 = row gr pair, d1 = row gr+8 pair); n in f32
        uint32_t ar[8][2], az[8][2];
        float    an[8][4];
        #pragma unroll
        for (int nt = 0; nt < 8; nt++) {
            ar[nt][0] = 0u; ar[nt][1] = 0u;
            az[nt][0] = 0u; az[nt][1] = 0u;
            an[nt][0] = 0.f; an[nt][1] = 0.f; an[nt][2] = 0.f; an[nt][3] = 0.f;
        }

        #pragma unroll 4
        for (int ks = 0; ks < 16; ks++) {
            const int slot = ks & 1;
            uint4 a0 = af[slot][0], a1 = af[slot][1], a2 = af[slot][2];
            if (ks < 14) {
                const uint4* qH = pH + (ks+2)*96;
                af[slot][0] = qH[0]; af[slot][1] = qH[32]; af[slot][2] = qH[64];
            }
            // B fragments: 64 batch rows = 4 ldsm4 (8 n-tiles)
            uint32_t bfh[16];
            #pragma unroll
            for (int np = 0; np < 4; np++) {
                uint32_t r4[4];
                ldsm4(r4, curb + (uint32_t)(np*(16*HROW) + ks*32) + rowoff);
                bfh[4*np+0] = r4[0]; bfh[4*np+1] = r4[1];
                bfh[4*np+2] = r4[2]; bfh[4*np+3] = r4[3];
            }
            #pragma unroll
            for (int nt = 0; nt < 8; nt++) {
                mma_f16acc(ar[nt][0], ar[nt][1],
                           a0.x,a0.y,a0.z,a0.w, bfh[2*nt], bfh[2*nt+1]);
                mma_f16acc(az[nt][0], az[nt][1],
                           a1.x,a1.y,a1.z,a1.w, bfh[2*nt], bfh[2*nt+1]);
                mma_f16(an[nt][0],an[nt][1],an[nt][2],an[nt][3],
                        a2.x,a2.y,a2.z,a2.w, bfh[2*nt], bfh[2*nt+1]);
            }
        }

        // refill A ring for next step; LDG latency hides behind epilogue
        af[0][0] = pH[0];    af[0][1] = pH[32];    af[0][2] = pH[64];
        af[1][0] = pH[96];   af[1][1] = pH[96+32]; af[1][2] = pH[96+64];

        // ---- epilogue: f16x2 gates + h update on (b, b+1) pairs ----
        {
            const unsigned short* CH = (const unsigned short*)(sm + cur);
            unsigned short* NH = (unsigned short*)(sm + nxt);
            const int jA = 16*w + gr;
            #pragma unroll
            for (int rp = 0; rp < 2; rp++) {
                const int j = jA + 8*rp;
                const __half2 brh = __float2half2_rn(0.5f*bsr[j]);
                const __half2 bzh = __float2half2_rn(0.5f*bsz[j]);
                const __half2 bhh = __float2half2_rn(bhn[j]);
                const __half2 bih = __float2half2_rn(bin[j]);
                #pragma unroll
                for (int nt = 0; nt < 8; nt++) {
                    const int b0 = nt*8 + 2*tig;
                    __half2 ar2 = *reinterpret_cast<__half2*>(&ar[nt][rp]);
                    __half2 az2 = *reinterpret_cast<__half2*>(&az[nt][rp]);
                    __half2 an2 = __floats2half2_rn(an[nt][2*rp], an[nt][2*rp+1]);
                    __half2 rr2 = __hfma2(tanh2(__hfma2(ar2, h05, brh)), h05, h05);
                    __half2 zz2 = __hfma2(tanh2(__hfma2(az2, h05, bzh)), h05, h05);
                    __half2 nn2 = tanh2(__hfma2(rr2, __hadd2(an2, bhh), bih));
                    uint32_t hw = (uint32_t)CH[b0*HP + j] | ((uint32_t)CH[(b0+1)*HP + j] << 16);
                    __half2 hold2 = *reinterpret_cast<__half2*>(&hw);
                    __half2 hnew2 = __hfma2(zz2, __hsub2(hold2, nn2), nn2);
                    uint32_t hv = *reinterpret_cast<uint32_t*>(&hnew2);
                    NH[b0*HP + j]     = (unsigned short)(hv & 0xffffu);
                    NH[(b0+1)*HP + j] = (unsigned short)(hv >> 16);
                }
            }
        }

        __syncthreads();   // h_next complete, visible to all

        // ---- output projection, spread over all 512 threads (4 per (m,o) pair) ----
        {
            const int pair = tid >> 2;          // 0..127 = 64 rows x 2 outputs
            const int m = pair >> 1, o = pair & 1, q = tid & 3;
            float s = 0.f;
            const uint4* hh = (const uint4*)(sm + nxt + (size_t)m*HROW) + q*8;
            const float* wq = ow + o*256 + q*64;
            #pragma unroll
            for (int i = 0; i < 8; i++) {
                uint4 Hv = hh[i];
                const __half2 h2[4] = {
                    *(const __half2*)&Hv.x, *(const __half2*)&Hv.y,
                    *(const __half2*)&Hv.z, *(const __half2*)&Hv.w };
                const float* wr = wq + i*8;
                #pragma unroll
                for (int p = 0; p < 4; p++) {
                    float2 e = __half22float2(h2[p]);
                    s += e.x * wr[2*p] + e.y * wr[2*p + 1];
                }
            }
            s += __shfl_xor_sync(0xffffffffu, s, 1);
            s += __shfl_xor_sync(0xffffffffu, s, 2);
            if (q == 0) obuf[(m*20 + (t % 20))*2 + o] = s + ob[o];
        }

        // ---- coalesced flush every 20 steps (180 = 9*20) ----
        if ((t % 20) == 19) {
            __syncthreads();
            const int m = tid >> 3, q = tid & 7;   // 64 rows x 8 threads
            float* dst = out + (size_t)(mbase + m)*360 + (t - 19)*2 + q*5;
            const float* src = obuf + m*40 + q*5;
            #pragma unroll
            for (int i = 0; i < 5; i++) dst[i] = src[i];
        }

        uint32_t tmp = cur; cur = nxt; nxt = tmp;
    }
}

extern "C" void kernel_launch(void* const* d_in, const int* in_sizes, int n_in,
                              void* d_out, int out_size)
{
    (void)in_sizes; (void)n_in; (void)out_size;
    const float* z     = (const float*)d_in[0];
    const float* fc_w  = (const float*)d_in[1];
    const float* fc_b  = (const float*)d_in[2];
    /* d_in[3] = w_ih unused: GRU input is all-zeros, gi == b_ih */
    const float* b_ih  = (const float*)d_in[4];
    const float* w_hh  = (const float*)d_in[5];
    const float* b_hh  = (const float*)d_in[6];
    const float* out_w = (const float*)d_in[7];
    const float* out_b = (const float*)d_in[8];

    prep_w<<<96, 256>>>(w_hh);

    cudaFuncSetAttribute(gru_hmma_kernel,
                         cudaFuncAttributeMaxDynamicSharedMemorySize, SMEM_SZ);
    gru_hmma_kernel<<<NCTA, NTHR, SMEM_SZ>>>(
        z, fc_w, fc_b, b_ih, b_hh, out_w, out_b, (float*)d_out);
}